// round 5
// baseline (speedup 1.0000x reference)
#include <cuda_runtime.h>
#include <cstdint>
#include <cstddef>

#define TSTEPS 1024
#define BSZ 128
#define DSZ 256
#define HSZ 512
#define CSZ 1000
#define CHUNK 128

// Scratch: x-projections, layout [t][gate][j][b] (b contiguous).
__device__ float g_P[(size_t)TSTEPS * 4 * HSZ * BSZ];
// Double-buffered hidden state, layout [j][b].
__device__ float g_h[2][HSZ * BSZ];
// Grid-wide barrier state.
__device__ unsigned g_bar_count;
__device__ unsigned g_bar_gen;

__device__ __forceinline__ float fast_sigmoid(float x) {
    return __fdividef(1.0f, 1.0f + __expf(-x));
}
__device__ __forceinline__ float fast_tanh(float x) {
    return __fdividef(2.0f, 1.0f + __expf(-2.0f * x)) - 1.0f;
}

// Packed f32x2 FMA: one fma-pipe slot = 2 FMAs (ptxas never emits this from C++).
#define FMA2(acc, a, b_) \
    asm("fma.rn.f32x2 %0, %1, %2, %0;" : "+l"(acc) : "l"(a), "l"(b_))

__device__ __forceinline__ unsigned long long dup2(float v) {
    unsigned long long d;
    asm("mov.b64 %0, {%1, %1};" : "=l"(d) : "f"(v));
    return d;
}
__device__ __forceinline__ float2 unpk(unsigned long long v) {
    float2 r;
    asm("mov.b64 {%0, %1}, %2;" : "=f"(r.x), "=f"(r.y) : "l"(v));
    return r;
}

__device__ __forceinline__ void grid_barrier(unsigned nb) {
    __syncthreads();
    if (threadIdx.x == 0) {
        __threadfence();
        unsigned gen = *(volatile unsigned*)&g_bar_gen;
        unsigned arrived = atomicAdd(&g_bar_count, 1u);
        if (arrived == nb - 1u) {
            atomicExch(&g_bar_count, 0u);
            __threadfence();
            atomicAdd(&g_bar_gen, 1u);
        } else {
            while (*(volatile unsigned*)&g_bar_gen == gen) {
                __nanosleep(32);
            }
        }
        __threadfence();
    }
    __syncthreads();
}

__device__ __forceinline__ void cp16(void* dst_smem, const void* src) {
    unsigned d = (unsigned)__cvta_generic_to_shared(dst_smem);
    asm volatile("cp.async.cg.shared.global [%0], [%1], 16;\n" :: "r"(d), "l"(src));
}

// ---------------------------------------------------------------------------
// Phase 1: P[t][g][j][b] = sum_d x[b][t][d] * Wx[g][d][j]
// grid: (8 j-tiles of 64, 4 gates, 1024 t), block 256.
// Accumulators packed over j-pairs (f32x2); x staged k-major for LDS.128.
// ---------------------------------------------------------------------------
__global__ __launch_bounds__(256) void k_xproj(
    const float* __restrict__ x,
    const float* __restrict__ W0, const float* __restrict__ W1,
    const float* __restrict__ W2, const float* __restrict__ W3)
{
    extern __shared__ float sm[];
    float* sW  = sm;            // [64 k][64 j]
    float* sXT = sm + 4096;     // [64 k][132] (b fast, pad 4)

    const int jt = blockIdx.x, g = blockIdx.y, t = blockIdx.z;
    const float* W = (g == 0) ? W0 : (g == 1) ? W1 : (g == 2) ? W2 : W3;
    const int tid = threadIdx.x;
    const int lane = tid & 31, warp = tid >> 5;
    const int j0 = warp * 8;   // 8 warps * 8 j
    const int b0 = lane * 4;   // 32 lanes * 4 b

    unsigned long long acc[4][4];   // [j-pair][b], packed over (j,j+1)
#pragma unroll
    for (int a = 0; a < 4; ++a)
#pragma unroll
        for (int bi = 0; bi < 4; ++bi) acc[a][bi] = 0ull;

    for (int kc = 0; kc < DSZ; kc += 64) {
        __syncthreads();
        for (int i = tid; i < 1024; i += 256) {
            int r = i >> 4, c4 = (i & 15) * 4;
            *(float4*)&sW[r * 64 + c4] =
                *(const float4*)&W[(size_t)(kc + r) * HSZ + jt * 64 + c4];
        }
        for (int i = tid; i < 2048; i += 256) {
            int b = i >> 4, d4 = (i & 15) * 4;
            float4 v = *(const float4*)&x[((size_t)b * TSTEPS + t) * DSZ + kc + d4];
            sXT[(d4 + 0) * 132 + b] = v.x;
            sXT[(d4 + 1) * 132 + b] = v.y;
            sXT[(d4 + 2) * 132 + b] = v.z;
            sXT[(d4 + 3) * 132 + b] = v.w;
        }
        __syncthreads();
#pragma unroll 4
        for (int k = 0; k < 64; ++k) {
            ulonglong2 wA = *(const ulonglong2*)&sW[k * 64 + j0];      // (j0,j1),(j2,j3)
            ulonglong2 wB = *(const ulonglong2*)&sW[k * 64 + j0 + 4];  // (j4,j5),(j6,j7)
            float4 xv = *(const float4*)&sXT[k * 132 + b0];
            unsigned long long x0 = dup2(xv.x), x1 = dup2(xv.y);
            unsigned long long x2 = dup2(xv.z), x3 = dup2(xv.w);
            FMA2(acc[0][0], x0, wA.x); FMA2(acc[0][1], x1, wA.x);
            FMA2(acc[0][2], x2, wA.x); FMA2(acc[0][3], x3, wA.x);
            FMA2(acc[1][0], x0, wA.y); FMA2(acc[1][1], x1, wA.y);
            FMA2(acc[1][2], x2, wA.y); FMA2(acc[1][3], x3, wA.y);
            FMA2(acc[2][0], x0, wB.x); FMA2(acc[2][1], x1, wB.x);
            FMA2(acc[2][2], x2, wB.x); FMA2(acc[2][3], x3, wB.x);
            FMA2(acc[3][0], x0, wB.y); FMA2(acc[3][1], x1, wB.y);
            FMA2(acc[3][2], x2, wB.y); FMA2(acc[3][3], x3, wB.y);
        }
    }
    const size_t obase = (((size_t)t * 4 + g) * HSZ + jt * 64 + j0) * BSZ + b0;
#pragma unroll
    for (int jp = 0; jp < 4; ++jp) {
        float2 p0 = unpk(acc[jp][0]), p1 = unpk(acc[jp][1]);
        float2 p2 = unpk(acc[jp][2]), p3 = unpk(acc[jp][3]);
        *(float4*)&g_P[obase + (size_t)(jp * 2 + 0) * BSZ] =
            make_float4(p0.x, p1.x, p2.x, p3.x);
        *(float4*)&g_P[obase + (size_t)(jp * 2 + 1) * BSZ] =
            make_float4(p0.y, p1.y, p2.y, p3.y);
    }
}

// ---------------------------------------------------------------------------
// Phase 2: persistent scan. 128 CTAs = 64 col-groups x 2 batch-halves.
// CTA (cg,bh): j in [cg*8, cg*8+8), b in [bh*64, bh*64+64).
// Thread (jp = tid>>6, b = tid&63): ALL 4 gates x j-pair x 1 batch.
// Cell state in registers; no gate exchange. Weights gate-interleaved in smem.
// SMEM floats: sh_W[512][32]=16384 | sh_h[2][128][64]=16384  (128 KB)
// ---------------------------------------------------------------------------
__global__ __launch_bounds__(256, 1) void k_rnn(
    const float* __restrict__ Wgh, const float* __restrict__ Wih,
    const float* __restrict__ Wfh, const float* __restrict__ Woh,
    const float* __restrict__ bgp, const float* __restrict__ bip,
    const float* __restrict__ bfp, const float* __restrict__ bop)
{
    extern __shared__ float sm[];
    float* sh_W = sm;            // 16384
    float* sh_h = sm + 16384;    // 2 x 8192

    const int ct = blockIdx.x;
    const int cg = ct >> 1;
    const int bh = ct & 1;
    const int j0 = cg * 8;
    const int bo = bh * 64;
    const int tid = threadIdx.x;
    const int jp = tid >> 6;        // 0..3 (j-pair)
    const int b  = tid & 63;
    const int bb = bo + b;
    const int jA = j0 + jp * 2;

    // Interleaved weights: sh_W[k*32 + jpp*8 + g*2 + jj] = Wg[k][j0 + jpp*2 + jj]
    {
        const float* Ws0 = Wgh; const float* Ws1 = Wih;
        const float* Ws2 = Wfh; const float* Ws3 = Woh;
        for (int i = tid; i < 16384; i += 256) {
            int k = i >> 5, r = i & 31;
            int jpp = r >> 3, g = (r >> 1) & 3, jj = r & 1;
            const float* Wg = (g == 0) ? Ws0 : (g == 1) ? Ws1 : (g == 2) ? Ws2 : Ws3;
            sh_W[i] = Wg[(size_t)k * HSZ + j0 + jpp * 2 + jj];
        }
    }
    float bias[8];
    bias[0] = bgp[jA]; bias[1] = bgp[jA + 1];
    bias[2] = bip[jA]; bias[3] = bip[jA + 1];
    bias[4] = bfp[jA]; bias[5] = bfp[jA + 1];
    bias[6] = bop[jA]; bias[7] = bop[jA + 1];

    // zero our rows of h[0]
    for (int i = tid; i < 512; i += 256) {
        int r = i >> 6, cc = i & 63;
        g_h[0][(size_t)(j0 + r) * BSZ + bo + cc] = 0.0f;
    }
    grid_barrier(gridDim.x);

    float c0 = 0.0f, c1 = 0.0f;
    const int ls = tid & 15;   // 16B slot in a 256B row
    const int lr = tid >> 4;   // 16 rows per pass

    for (int t = 0; t < TSTEPS; ++t) {
        const float* hb = g_h[t & 1];
        float* hn = g_h[(t + 1) & 1];

        // x-projection prefetch (used only at epilogue; latency hidden by k-loop)
        float p[8];
        {
            const float* Pt = g_P + (size_t)t * 4 * HSZ * BSZ;
#pragma unroll
            for (int g = 0; g < 4; ++g) {
                p[g * 2 + 0] = __ldg(&Pt[((size_t)g * HSZ + jA + 0) * BSZ + bb]);
                p[g * 2 + 1] = __ldg(&Pt[((size_t)g * HSZ + jA + 1) * BSZ + bb]);
            }
        }

        unsigned long long a0 = 0, a1 = 0, a2 = 0, a3 = 0;  // packed (jA, jA+1) per gate

        // prefetch chunk 0
#pragma unroll
        for (int r = 0; r < 8; ++r) {
            int row = lr + r * 16;
            cp16(&sh_h[row * 64 + ls * 4], &hb[(size_t)row * BSZ + bo + ls * 4]);
        }
        asm volatile("cp.async.commit_group;");

        for (int c = 0; c < 4; ++c) {
            if (c < 3) {
                float* dst = sh_h + ((c + 1) & 1) * 8192;
                const float* src = hb + (size_t)(c + 1) * CHUNK * BSZ;
#pragma unroll
                for (int r = 0; r < 8; ++r) {
                    int row = lr + r * 16;
                    cp16(&dst[row * 64 + ls * 4], &src[(size_t)row * BSZ + bo + ls * 4]);
                }
                asm volatile("cp.async.commit_group;");
                asm volatile("cp.async.wait_group 1;");
            } else {
                asm volatile("cp.async.wait_group 0;");
            }
            __syncthreads();
            const float* hs = sh_h + (c & 1) * 8192;
            const float* wp = sh_W + c * CHUNK * 32 + jp * 8;
#pragma unroll 8
            for (int k = 0; k < CHUNK; ++k) {
                unsigned long long hd = dup2(hs[k * 64 + b]);
                ulonglong2 wA = *(const ulonglong2*)(wp + k * 32);      // g,i
                ulonglong2 wB = *(const ulonglong2*)(wp + k * 32 + 4);  // f,o
                FMA2(a0, hd, wA.x);
                FMA2(a1, hd, wA.y);
                FMA2(a2, hd, wB.x);
                FMA2(a3, hd, wB.y);
            }
            __syncthreads();
        }

        float2 vg = unpk(a0), vi = unpk(a1), vf = unpk(a2), vo = unpk(a3);
        float gg0 = fast_tanh   (vg.x + p[0] + bias[0]);
        float gg1 = fast_tanh   (vg.y + p[1] + bias[1]);
        float ii0 = fast_sigmoid(vi.x + p[2] + bias[2]);
        float ii1 = fast_sigmoid(vi.y + p[3] + bias[3]);
        float ff0 = fast_sigmoid(vf.x + p[4] + bias[4]);
        float ff1 = fast_sigmoid(vf.y + p[5] + bias[5]);
        float oo0 = fast_sigmoid(vo.x + p[6] + bias[6]);
        float oo1 = fast_sigmoid(vo.y + p[7] + bias[7]);
        c0 = gg0 * ii0 + c0 * ff0;
        c1 = gg1 * ii1 + c1 * ff1;
        hn[(size_t)jA * BSZ + bb]       = fast_tanh(c0) * oo0;
        hn[(size_t)(jA + 1) * BSZ + bb] = fast_tanh(c1) * oo1;

        grid_barrier(gridDim.x);
    }
}

// ---------------------------------------------------------------------------
// Phase 3: out[b][c] = h_final[b] . Wph[:,c] + bp[c].
// ---------------------------------------------------------------------------
__global__ __launch_bounds__(128) void k_out(
    const float* __restrict__ Wp, const float* __restrict__ bp,
    float* __restrict__ out)
{
    int c = blockIdx.x;
    int b = threadIdx.x;
    const float* h = g_h[0];
    float acc = 0.0f;
#pragma unroll 8
    for (int k = 0; k < HSZ; ++k)
        acc += h[k * BSZ + b] * Wp[(size_t)k * CSZ + c];
    out[b * CSZ + c] = acc + bp[c];
}

// ---------------------------------------------------------------------------

extern "C" void kernel_launch(void* const* d_in, const int* in_sizes, int n_in,
                              void* d_out, int out_size) {
    const float* x   = (const float*)d_in[0];
    const float* Wgx = (const float*)d_in[1];
    const float* Wgh = (const float*)d_in[2];
    const float* bg  = (const float*)d_in[3];
    const float* Wix = (const float*)d_in[4];
    const float* Wih = (const float*)d_in[5];
    const float* bi  = (const float*)d_in[6];
    const float* Wfx = (const float*)d_in[7];
    const float* Wfh = (const float*)d_in[8];
    const float* bf  = (const float*)d_in[9];
    const float* Wox = (const float*)d_in[10];
    const float* Woh = (const float*)d_in[11];
    const float* bo  = (const float*)d_in[12];
    const float* Wph = (const float*)d_in[13];
    const float* bp  = (const float*)d_in[14];
    float* out = (float*)d_out;

    (void)in_sizes; (void)n_in; (void)out_size;

    const int smem1 = (4096 + 64 * 132) * 4;   // 50176 B
    const int smem2 = 32768 * 4;               // 131072 B
    cudaFuncSetAttribute(k_xproj, cudaFuncAttributeMaxDynamicSharedMemorySize, smem1);
    cudaFuncSetAttribute(k_rnn,   cudaFuncAttributeMaxDynamicSharedMemorySize, smem2);

    dim3 g1(8, 4, TSTEPS);
    k_xproj<<<g1, 256, smem1>>>(x, Wgx, Wix, Wfx, Wox);
    k_rnn<<<128, 256, smem2>>>(Wgh, Wih, Wfh, Woh, bg, bi, bf, bo);
    k_out<<<CSZ, 128>>>(Wph, bp, out);
}

// round 6
// speedup vs baseline: 1.3756x; 1.3756x over previous
#include <cuda_runtime.h>
#include <cstdint>
#include <cstddef>

#define TSTEPS 1024
#define BSZ 128
#define DSZ 256
#define HSZ 512
#define CSZ 1000

// Scratch: x-projections, layout [t][gate][j][b] (b contiguous).
__device__ float g_P[(size_t)TSTEPS * 4 * HSZ * BSZ];
// Double-buffered hidden state, layout [b][k] (k contiguous), tf32-rounded values.
__device__ float g_h2[2][BSZ * HSZ];
// Barrier state.
__device__ unsigned g_bar_count;
__device__ unsigned g_bar_gen;
__device__ unsigned g_flags[128 * 8];   // one flag per CTA, 32B spacing

__device__ __forceinline__ float fast_sigmoid(float x) {
    return __fdividef(1.0f, 1.0f + __expf(-x));
}
__device__ __forceinline__ float fast_tanh(float x) {
    return __fdividef(2.0f, 1.0f + __expf(-2.0f * x)) - 1.0f;
}

__device__ __forceinline__ unsigned cvt_tf32(float f) {
    unsigned u;
    asm("cvt.rna.tf32.f32 %0, %1;" : "=r"(u) : "f"(f));
    return u;
}

#define FMA2(acc, a, b_) \
    asm("fma.rn.f32x2 %0, %1, %2, %0;" : "+l"(acc) : "l"(a), "l"(b_))
__device__ __forceinline__ unsigned long long dup2(float v) {
    unsigned long long d;
    asm("mov.b64 %0, {%1, %1};" : "=l"(d) : "f"(v));
    return d;
}
__device__ __forceinline__ float2 unpk(unsigned long long v) {
    float2 r;
    asm("mov.b64 {%0, %1}, %2;" : "=f"(r.x), "=f"(r.y) : "l"(v));
    return r;
}

// one-shot init barrier (atomic counter; used once per run)
__device__ __forceinline__ void grid_barrier(unsigned nb) {
    __syncthreads();
    if (threadIdx.x == 0) {
        __threadfence();
        unsigned gen = *(volatile unsigned*)&g_bar_gen;
        unsigned arrived = atomicAdd(&g_bar_count, 1u);
        if (arrived == nb - 1u) {
            atomicExch(&g_bar_count, 0u);
            __threadfence();
            atomicAdd(&g_bar_gen, 1u);
        } else {
            while (*(volatile unsigned*)&g_bar_gen == gen) { __nanosleep(32); }
        }
        __threadfence();
    }
    __syncthreads();
}

// per-step flag barrier: monotone generation, parallel arrivals
__device__ __forceinline__ void flag_barrier(int ct, unsigned gen) {
    __syncthreads();
    if (threadIdx.x == 0) {
        __threadfence();                      // h stores visible before flag
        *(volatile unsigned*)&g_flags[ct * 8] = gen;
    }
    if (threadIdx.x < 32) {
#pragma unroll
        for (int i = 0; i < 4; ++i) {
            volatile unsigned* f = &g_flags[(threadIdx.x + i * 32) * 8];
            while (*f < gen) { }
        }
    }
    __syncthreads();
}

__device__ __forceinline__ void cp16(void* dst_smem, const void* src) {
    unsigned d = (unsigned)__cvta_generic_to_shared(dst_smem);
    asm volatile("cp.async.cg.shared.global [%0], [%1], 16;\n" :: "r"(d), "l"(src));
}

#define MMA_TF32(c0,c1,c2,c3, a0,a1,a2,a3, b0,b1) \
    asm("mma.sync.aligned.m16n8k8.row.col.f32.tf32.tf32.f32 " \
        "{%0,%1,%2,%3}, {%4,%5,%6,%7}, {%8,%9}, {%0,%1,%2,%3};" \
        : "+f"(c0), "+f"(c1), "+f"(c2), "+f"(c3) \
        : "r"(a0), "r"(a1), "r"(a2), "r"(a3), "r"(b0), "r"(b1))

// ---------------------------------------------------------------------------
// Phase 1: P[t][g][j][b] = sum_d x[b][t][d] * Wx[g][d][j]   (unchanged)
// ---------------------------------------------------------------------------
__global__ __launch_bounds__(256) void k_xproj(
    const float* __restrict__ x,
    const float* __restrict__ W0, const float* __restrict__ W1,
    const float* __restrict__ W2, const float* __restrict__ W3)
{
    extern __shared__ float sm[];
    float* sW  = sm;            // [64 k][64 j]
    float* sXT = sm + 4096;     // [64 k][132]

    const int jt = blockIdx.x, g = blockIdx.y, t = blockIdx.z;
    const float* W = (g == 0) ? W0 : (g == 1) ? W1 : (g == 2) ? W2 : W3;
    const int tid = threadIdx.x;
    const int lane = tid & 31, warp = tid >> 5;
    const int j0 = warp * 8;
    const int b0 = lane * 4;

    unsigned long long acc[4][4];
#pragma unroll
    for (int a = 0; a < 4; ++a)
#pragma unroll
        for (int bi = 0; bi < 4; ++bi) acc[a][bi] = 0ull;

    for (int kc = 0; kc < DSZ; kc += 64) {
        __syncthreads();
        for (int i = tid; i < 1024; i += 256) {
            int r = i >> 4, c4 = (i & 15) * 4;
            *(float4*)&sW[r * 64 + c4] =
                *(const float4*)&W[(size_t)(kc + r) * HSZ + jt * 64 + c4];
        }
        for (int i = tid; i < 2048; i += 256) {
            int b = i >> 4, d4 = (i & 15) * 4;
            float4 v = *(const float4*)&x[((size_t)b * TSTEPS + t) * DSZ + kc + d4];
            sXT[(d4 + 0) * 132 + b] = v.x;
            sXT[(d4 + 1) * 132 + b] = v.y;
            sXT[(d4 + 2) * 132 + b] = v.z;
            sXT[(d4 + 3) * 132 + b] = v.w;
        }
        __syncthreads();
#pragma unroll 4
        for (int k = 0; k < 64; ++k) {
            ulonglong2 wA = *(const ulonglong2*)&sW[k * 64 + j0];
            ulonglong2 wB = *(const ulonglong2*)&sW[k * 64 + j0 + 4];
            float4 xv = *(const float4*)&sXT[k * 132 + b0];
            unsigned long long x0 = dup2(xv.x), x1 = dup2(xv.y);
            unsigned long long x2 = dup2(xv.z), x3 = dup2(xv.w);
            FMA2(acc[0][0], x0, wA.x); FMA2(acc[0][1], x1, wA.x);
            FMA2(acc[0][2], x2, wA.x); FMA2(acc[0][3], x3, wA.x);
            FMA2(acc[1][0], x0, wA.y); FMA2(acc[1][1], x1, wA.y);
            FMA2(acc[1][2], x2, wA.y); FMA2(acc[1][3], x3, wA.y);
            FMA2(acc[2][0], x0, wB.x); FMA2(acc[2][1], x1, wB.x);
            FMA2(acc[2][2], x2, wB.x); FMA2(acc[2][3], x3, wB.x);
            FMA2(acc[3][0], x0, wB.y); FMA2(acc[3][1], x1, wB.y);
            FMA2(acc[3][2], x2, wB.y); FMA2(acc[3][3], x3, wB.y);
        }
    }
    const size_t obase = (((size_t)t * 4 + g) * HSZ + jt * 64 + j0) * BSZ + b0;
#pragma unroll
    for (int jp = 0; jp < 4; ++jp) {
        float2 p0 = unpk(acc[jp][0]), p1 = unpk(acc[jp][1]);
        float2 p2 = unpk(acc[jp][2]), p3 = unpk(acc[jp][3]);
        *(float4*)&g_P[obase + (size_t)(jp * 2 + 0) * BSZ] =
            make_float4(p0.x, p1.x, p2.x, p3.x);
        *(float4*)&g_P[obase + (size_t)(jp * 2 + 1) * BSZ] =
            make_float4(p0.y, p1.y, p2.y, p3.y);
    }
}

// ---------------------------------------------------------------------------
// Phase 2: persistent tf32-mma scan. 128 CTAs, 256 threads (8 warps).
// CTA ct: rows m = jj*4+g for jj in [0,4) (j = ct*4+jj), g in [0,4); all 128 b.
// Warp w: batch cols [w*16, w*16+16) (2 n-tiles), K = 512 (64 k-steps).
// SMEM (floats): sh_A[64][32][4]=8192 | sh_h[2][128][132]=33792 | sh_E[16][130]=2080
// ---------------------------------------------------------------------------
__global__ __launch_bounds__(256, 1) void k_rnn(
    const float* __restrict__ Wgh, const float* __restrict__ Wih,
    const float* __restrict__ Wfh, const float* __restrict__ Woh,
    const float* __restrict__ bgp, const float* __restrict__ bip,
    const float* __restrict__ bfp, const float* __restrict__ bop)
{
    extern __shared__ float sm[];
    float*    sh_A = sm;                       // 8192 f (pre-swizzled tf32 weights)
    float*    sh_h = sm + 8192;                // 2 x 128 x 132
    float*    sh_E = sm + 8192 + 2 * 128 * 132; // 16 x 130 exchange

    const int ct  = blockIdx.x;
    const int j0  = ct * 4;
    const int tid = threadIdx.x;
    const int w   = tid >> 5;
    const int lane = tid & 31;
    const int gid = lane >> 2;     // 0..7
    const int tg  = lane & 3;      // 0..3
    const int n0  = w * 16;

    // --- build pre-swizzled A fragments (once) ---
    {
        const float* Wt[4] = {Wgh, Wih, Wfh, Woh};
        for (int idx = tid; idx < 8192; idx += 256) {
            int ks = idx >> 7;            // 0..63
            int ln = (idx >> 2) & 31;
            int q  = idx & 3;
            int gg = ln >> 2, tt = ln & 3;
            int m  = gg + (q & 1) * 8;            // row 0..15
            int k  = ks * 8 + tt + (q >> 1) * 4;  // col 0..511
            int gate = m & 3, jj = m >> 2;
            float v = Wt[gate][(size_t)k * HSZ + j0 + jj];
            ((unsigned*)sh_A)[idx] = cvt_tf32(v);
        }
    }
    // bias per D-frag row
    float biasA, biasB;
    {
        const float* Bt[4] = {bgp, bip, bfp, bop};
        int mA = gid, mB = gid + 8;
        biasA = Bt[mA & 3][j0 + (mA >> 2)];
        biasB = Bt[mB & 3][j0 + (mB >> 2)];
    }

    // zero h[0] slice + own flag, then one-shot init barrier
    for (int i = tid; i < 512; i += 256) g_h2[0][ct * 512 + i] = 0.0f;
    if (tid == 0) *(volatile unsigned*)&g_flags[ct * 8] = 0u;
    grid_barrier(gridDim.x);

    // cell state for this thread's 2 (jj, b) outputs
    float cst0 = 0.0f, cst1 = 0.0f;
    const int e_jj = lane >> 3;                  // 0..3
    const int e_b  = n0 + (lane & 7) * 2;        // batch of first output

    // cp.async indexing
    const int cp_row0 = tid >> 5;                // 0..7, step 8
    const int cp_slot = (tid & 31) * 4;          // float offset in row

    // P prefetch for t=0
    float2 pf[4];
    {
        const float* Pt = g_P;
#pragma unroll
        for (int tile = 0; tile < 2; ++tile) {
            int mA = gid, mB = gid + 8;
            int colb = n0 + tile * 8 + tg * 2;
            pf[tile * 2 + 0] = *(const float2*)&Pt[(((size_t)(mA & 3)) * HSZ + j0 + (mA >> 2)) * BSZ + colb];
            pf[tile * 2 + 1] = *(const float2*)&Pt[(((size_t)(mB & 3)) * HSZ + j0 + (mB >> 2)) * BSZ + colb];
        }
    }

    for (int t = 0; t < TSTEPS; ++t) {
        const float* hb = g_h2[t & 1];
        float* hn = g_h2[(t + 1) & 1];

        // init accumulators from prefetched P + bias
        float c00 = pf[0].x + biasA, c01 = pf[0].y + biasA;
        float c02 = pf[1].x + biasB, c03 = pf[1].y + biasB;
        float c10 = pf[2].x + biasA, c11 = pf[2].y + biasA;
        float c12 = pf[3].x + biasB, c13 = pf[3].y + biasB;

        // prefetch P for t+1 (static data, overlaps mma)
        if (t + 1 < TSTEPS) {
            const float* Pt = g_P + (size_t)(t + 1) * 4 * HSZ * BSZ;
#pragma unroll
            for (int tile = 0; tile < 2; ++tile) {
                int mA = gid, mB = gid + 8;
                int colb = n0 + tile * 8 + tg * 2;
                pf[tile * 2 + 0] = *(const float2*)&Pt[(((size_t)(mA & 3)) * HSZ + j0 + (mA >> 2)) * BSZ + colb];
                pf[tile * 2 + 1] = *(const float2*)&Pt[(((size_t)(mB & 3)) * HSZ + j0 + (mB >> 2)) * BSZ + colb];
            }
        }

        // stage chunk 0: h[b][k-chunk] rows, 512B each
#pragma unroll
        for (int r = 0; r < 16; ++r) {
            int row = cp_row0 + r * 8;
            cp16(&sh_h[row * 132 + cp_slot], &hb[(size_t)row * HSZ + cp_slot]);
        }
        asm volatile("cp.async.commit_group;");

        for (int c = 0; c < 4; ++c) {
            if (c < 3) {
                float* dst = sh_h + ((c + 1) & 1) * (128 * 132);
                const float* src = hb + (c + 1) * 128;
#pragma unroll
                for (int r = 0; r < 16; ++r) {
                    int row = cp_row0 + r * 8;
                    cp16(&dst[row * 132 + cp_slot], &src[(size_t)row * HSZ + cp_slot]);
                }
                asm volatile("cp.async.commit_group;");
                asm volatile("cp.async.wait_group 1;");
            } else {
                asm volatile("cp.async.wait_group 0;");
            }
            __syncthreads();
            const float* hs = sh_h + (c & 1) * (128 * 132);
            const unsigned* Aq = (const unsigned*)sh_A + c * 16 * 128;
#pragma unroll
            for (int kk = 0; kk < 16; ++kk) {
                uint4 a = *(const uint4*)&Aq[kk * 128 + lane * 4];
                int kb = kk * 8 + tg;
                unsigned b00 = ((const unsigned*)hs)[(n0 + gid) * 132 + kb];
                unsigned b01 = ((const unsigned*)hs)[(n0 + gid) * 132 + kb + 4];
                MMA_TF32(c00, c01, c02, c03, a.x, a.y, a.z, a.w, b00, b01);
                unsigned b10 = ((const unsigned*)hs)[(n0 + 8 + gid) * 132 + kb];
                unsigned b11 = ((const unsigned*)hs)[(n0 + 8 + gid) * 132 + kb + 4];
                MMA_TF32(c10, c11, c12, c13, a.x, a.y, a.z, a.w, b10, b11);
            }
            __syncthreads();
        }

        // exchange: D -> sh_E[m][130], warp-private n-range
        {
            float* E = sh_E;
            *(float2*)&E[gid * 130 + n0 + tg * 2]            = make_float2(c00, c01);
            *(float2*)&E[(gid + 8) * 130 + n0 + tg * 2]      = make_float2(c02, c03);
            *(float2*)&E[gid * 130 + n0 + 8 + tg * 2]        = make_float2(c10, c11);
            *(float2*)&E[(gid + 8) * 130 + n0 + 8 + tg * 2]  = make_float2(c12, c13);
        }
        __syncwarp();

        // epilogue: combine gates for (e_jj, e_b) and (e_jj, e_b+1)
#pragma unroll
        for (int v = 0; v < 2; ++v) {
            int b = e_b + v;
            float pg = sh_E[(e_jj * 4 + 0) * 130 + b];
            float pi = sh_E[(e_jj * 4 + 1) * 130 + b];
            float pfr= sh_E[(e_jj * 4 + 2) * 130 + b];
            float po = sh_E[(e_jj * 4 + 3) * 130 + b];
            float gv = fast_tanh(pg);
            float iv = fast_sigmoid(pi);
            float fv = fast_sigmoid(pfr);
            float ov = fast_sigmoid(po);
            float& cs = v ? cst1 : cst0;
            cs = gv * iv + cs * fv;
            float hv = fast_tanh(cs) * ov;
            ((unsigned*)hn)[(size_t)b * HSZ + j0 + e_jj] = cvt_tf32(hv);
        }
        __syncwarp();

        flag_barrier(ct, (unsigned)(t + 1));
    }
}

// ---------------------------------------------------------------------------
// Phase 3: out[b][c] = h_final[b] . Wph[:,c] + bp[c].
// grid(128 b), block(256 over c). h cached in smem.
// ---------------------------------------------------------------------------
__global__ __launch_bounds__(256) void k_out(
    const float* __restrict__ Wp, const float* __restrict__ bp,
    float* __restrict__ out)
{
    __shared__ float sh[HSZ];
    int b = blockIdx.x;
    const float* h = g_h2[0] + (size_t)b * HSZ;   // t=1023 writes buffer (1024&1)=0
    for (int i = threadIdx.x; i < HSZ; i += 256) sh[i] = h[i];
    __syncthreads();
    for (int c = threadIdx.x; c < CSZ; c += 256) {
        float acc = 0.0f;
#pragma unroll 8
        for (int k = 0; k < HSZ; ++k)
            acc += sh[k] * Wp[(size_t)k * CSZ + c];
        out[b * CSZ + c] = acc + bp[c];
    }
}

// ---------------------------------------------------------------------------

extern "C" void kernel_launch(void* const* d_in, const int* in_sizes, int n_in,
                              void* d_out, int out_size) {
    const float* x   = (const float*)d_in[0];
    const float* Wgx = (const float*)d_in[1];
    const float* Wgh = (const float*)d_in[2];
    const float* bg  = (const float*)d_in[3];
    const float* Wix = (const float*)d_in[4];
    const float* Wih = (const float*)d_in[5];
    const float* bi  = (const float*)d_in[6];
    const float* Wfx = (const float*)d_in[7];
    const float* Wfh = (const float*)d_in[8];
    const float* bf  = (const float*)d_in[9];
    const float* Wox = (const float*)d_in[10];
    const float* Woh = (const float*)d_in[11];
    const float* bo  = (const float*)d_in[12];
    const float* Wph = (const float*)d_in[13];
    const float* bp  = (const float*)d_in[14];
    float* out = (float*)d_out;

    (void)in_sizes; (void)n_in; (void)out_size;

    const int smem1 = (4096 + 64 * 132) * 4;                  // 50176 B
    const int smem2 = (8192 + 2 * 128 * 132 + 16 * 130) * 4;  // 176256 B
    cudaFuncSetAttribute(k_xproj, cudaFuncAttributeMaxDynamicSharedMemorySize, smem1);
    cudaFuncSetAttribute(k_rnn,   cudaFuncAttributeMaxDynamicSharedMemorySize, smem2);

    dim3 g1(8, 4, TSTEPS);
    k_xproj<<<g1, 256, smem1>>>(x, Wgx, Wix, Wfx, Wox);
    k_rnn<<<128, 256, smem2>>>(Wgh, Wih, Wfh, Woh, bg, bi, bf, bo);
    k_out<<<128, 256>>>(Wph, bp, out);
}

// round 7
// speedup vs baseline: 2.4580x; 1.7868x over previous
#include <cuda_runtime.h>
#include <cstdint>
#include <cstddef>

#define TSTEPS 1024
#define BSZ 128
#define DSZ 256
#define HSZ 512
#define CSZ 1000

// x-projections, layout [t][gate][j][b] (b contiguous).  1 GB
__device__ float g_P[(size_t)TSTEPS * 4 * HSZ * BSZ];
// Double-buffered hidden state, layout [b][j], tf32-rounded values.
__device__ float g_h2[2][BSZ * HSZ];
// Pre-converted tf32 operands
__device__ unsigned g_Wt32[2048 * 256];                   // [g*512+j][d]
__device__ unsigned g_xt32[(size_t)TSTEPS * BSZ * DSZ];   // [t][b][d]  128 MB
// Barrier state
__device__ unsigned g_bar_count;
__device__ unsigned g_bar_gen;
__device__ unsigned g_flags[128 * 8];

__device__ __forceinline__ float fast_sigmoid(float x) {
    return __fdividef(1.0f, 1.0f + __expf(-x));
}
__device__ __forceinline__ float fast_tanh(float x) {
    return __fdividef(2.0f, 1.0f + __expf(-2.0f * x)) - 1.0f;
}
__device__ __forceinline__ unsigned cvt_tf32(float f) {
    unsigned u;
    asm("cvt.rna.tf32.f32 %0, %1;" : "=r"(u) : "f"(f));
    return u;
}

__device__ __forceinline__ void grid_barrier(unsigned nb) {
    __syncthreads();
    if (threadIdx.x == 0) {
        __threadfence();
        unsigned gen = *(volatile unsigned*)&g_bar_gen;
        unsigned arrived = atomicAdd(&g_bar_count, 1u);
        if (arrived == nb - 1u) {
            atomicExch(&g_bar_count, 0u);
            __threadfence();
            atomicAdd(&g_bar_gen, 1u);
        } else {
            while (*(volatile unsigned*)&g_bar_gen == gen) { __nanosleep(32); }
        }
        __threadfence();
    }
    __syncthreads();
}

// 32-CTA group barrier: CTAs with same ng (ct & 3). One flag per CTA.
__device__ __forceinline__ void flag_barrier_grp(int ct, int ng, unsigned gen) {
    __syncthreads();
    if (threadIdx.x == 0) {
        __threadfence();
        *(volatile unsigned*)&g_flags[ct * 8] = gen;
    }
    if (threadIdx.x < 32) {
        volatile unsigned* f = &g_flags[(threadIdx.x * 4 + ng) * 8];
        while (*f < gen) { }
    }
    __syncthreads();
}

__device__ __forceinline__ void cp16(void* dst_smem, const void* src) {
    unsigned d = (unsigned)__cvta_generic_to_shared(dst_smem);
    asm volatile("cp.async.cg.shared.global [%0], [%1], 16;\n" :: "r"(d), "l"(src));
}

#define MMA_TF32(c0,c1,c2,c3, a0,a1,a2,a3, b0,b1) \
    asm("mma.sync.aligned.m16n8k8.row.col.f32.tf32.tf32.f32 " \
        "{%0,%1,%2,%3}, {%4,%5,%6,%7}, {%8,%9}, {%0,%1,%2,%3};" \
        : "+f"(c0), "+f"(c1), "+f"(c2), "+f"(c3) \
        : "r"(a0), "r"(a1), "r"(a2), "r"(a3), "r"(b0), "r"(b1))

// ---------------------------------------------------------------------------
// Prep: W -> tf32 [M=g*512+j][d]
// ---------------------------------------------------------------------------
__global__ __launch_bounds__(256) void k_prep_w(
    const float* __restrict__ W0, const float* __restrict__ W1,
    const float* __restrict__ W2, const float* __restrict__ W3)
{
    int M = blockIdx.x;
    int g = M >> 9, j = M & 511;
    const float* W = (g == 0) ? W0 : (g == 1) ? W1 : (g == 2) ? W2 : W3;
    int d = threadIdx.x;
    g_Wt32[(size_t)M * 256 + d] = cvt_tf32(W[(size_t)d * HSZ + j]);
}

// Prep: x -> tf32 [t][b][d]
__global__ __launch_bounds__(64) void k_prep_x(const float* __restrict__ x)
{
    int t = blockIdx.x, b = blockIdx.y;
    int d4 = threadIdx.x * 4;
    float4 v = *(const float4*)&x[((size_t)b * TSTEPS + t) * DSZ + d4];
    uint4 o;
    o.x = cvt_tf32(v.x); o.y = cvt_tf32(v.y);
    o.z = cvt_tf32(v.z); o.w = cvt_tf32(v.w);
    *(uint4*)&g_xt32[((size_t)t * BSZ + b) * DSZ + d4] = o;
}

// ---------------------------------------------------------------------------
// Phase 1: tf32-mma GEMM. P[t][M][b] = sum_d Wt32[M][d] * xt32[t][b][d]
// grid (16 m-tiles, 1024 t), 256 threads. Tile M=128, N=128, K=256 (4 chunks).
// smem: sA[2][128][68] + sB[2][128][68] uints = 139264 B.
// ---------------------------------------------------------------------------
__global__ __launch_bounds__(256, 1) void k_xproj2()
{
    extern __shared__ unsigned smu[];
    unsigned* sA = smu;            // 2 x 8704
    unsigned* sB = smu + 17408;    // 2 x 8704

    const int M0 = blockIdx.x * 128;
    const int t  = blockIdx.y;
    const int tid = threadIdx.x;
    const int w = tid >> 5, lane = tid & 31;
    const int gp = lane >> 2, tg = lane & 3;

    float acc[16][4];
#pragma unroll
    for (int f = 0; f < 16; ++f)
#pragma unroll
        for (int q = 0; q < 4; ++q) acc[f][q] = 0.0f;

    const unsigned* Asrc = g_Wt32 + (size_t)M0 * 256;
    const unsigned* Bsrc = g_xt32 + (size_t)t * BSZ * DSZ;

    // stage chunk 0 into buffer 0
#pragma unroll
    for (int i = 0; i < 8; ++i) {
        int linear = tid + i * 256;
        int row = linear >> 4, seg = (linear & 15) * 4;
        cp16(&sA[row * 68 + seg], &Asrc[row * 256 + seg]);
        cp16(&sB[row * 68 + seg], &Bsrc[row * 256 + seg]);
    }
    asm volatile("cp.async.commit_group;");

    for (int c = 0; c < 4; ++c) {
        if (c < 3) {
            int kc = (c + 1) * 64;
            unsigned* dA = sA + ((c + 1) & 1) * 8704;
            unsigned* dB = sB + ((c + 1) & 1) * 8704;
#pragma unroll
            for (int i = 0; i < 8; ++i) {
                int linear = tid + i * 256;
                int row = linear >> 4, seg = (linear & 15) * 4;
                cp16(&dA[row * 68 + seg], &Asrc[row * 256 + kc + seg]);
                cp16(&dB[row * 68 + seg], &Bsrc[row * 256 + kc + seg]);
            }
            asm volatile("cp.async.commit_group;");
            asm volatile("cp.async.wait_group 1;");
        } else {
            asm volatile("cp.async.wait_group 0;");
        }
        __syncthreads();
        const unsigned* A = sA + (c & 1) * 8704;
        const unsigned* B = sB + (c & 1) * 8704;
        const int rA = (w * 16 + gp) * 68, rB = (w * 16 + gp + 8) * 68;
#pragma unroll
        for (int ksl = 0; ksl < 8; ++ksl) {
            int k0 = ksl * 8 + tg;
            unsigned a0 = A[rA + k0];
            unsigned a1 = A[rB + k0];
            unsigned a2 = A[rA + k0 + 4];
            unsigned a3 = A[rB + k0 + 4];
#pragma unroll
            for (int f = 0; f < 16; ++f) {
                unsigned b0 = B[(f * 8 + gp) * 68 + k0];
                unsigned b1 = B[(f * 8 + gp) * 68 + k0 + 4];
                MMA_TF32(acc[f][0], acc[f][1], acc[f][2], acc[f][3],
                         a0, a1, a2, a3, b0, b1);
            }
        }
        __syncthreads();
    }

    const size_t rbase = ((size_t)t * 2048 + M0 + w * 16 + gp) * 128;
#pragma unroll
    for (int f = 0; f < 16; ++f) {
        *(float2*)&g_P[rbase + f * 8 + tg * 2] =
            make_float2(acc[f][0], acc[f][1]);
        *(float2*)&g_P[rbase + (size_t)8 * 128 + f * 8 + tg * 2] =
            make_float2(acc[f][2], acc[f][3]);
    }
}

// ---------------------------------------------------------------------------
// Phase 2: persistent tf32-mma scan. 128 CTAs = 32 row-groups x 4 batch-groups.
// CTA (mg = ct>>2, ng = ct&3): rows m = jj*4+g, j = mg*16+jj (16 j x 4 gates),
// batches b in [ng*32, ng*32+32). 8 warps: mt = w&3 (m16 tile), nh = w>>2 (n16).
// SMEM floats: A 32768 | h 32*516=16512 | E 64*34=2176  -> 205824 B
// ---------------------------------------------------------------------------
__global__ __launch_bounds__(256, 1) void k_rnn2(
    const float* __restrict__ Wgh, const float* __restrict__ Wih,
    const float* __restrict__ Wfh, const float* __restrict__ Woh,
    const float* __restrict__ bgp, const float* __restrict__ bip,
    const float* __restrict__ bfp, const float* __restrict__ bop)
{
    extern __shared__ float sm[];
    unsigned* sAu = (unsigned*)sm;          // 32768
    float* sh_h = sm + 32768;               // 16512
    float* sh_E = sm + 32768 + 16512;       // 2176

    const int ct = blockIdx.x;
    const int mg = ct >> 2, ng = ct & 3;
    const int j0 = mg * 16;
    const int nbase = ng * 32;
    const int tid = threadIdx.x;
    const int w = tid >> 5, lane = tid & 31;
    const int mt = w & 3, nh = w >> 2;
    const int gp = lane >> 2, tg = lane & 3;

    // build pre-swizzled tf32 A fragments (once)
    {
        const float* Wt[4] = {Wgh, Wih, Wfh, Woh};
        for (int idx = tid; idx < 32768; idx += 256) {
            int mtb = idx >> 13;
            int rem = idx & 8191;
            int ks = rem >> 7;
            int ln = (rem >> 2) & 31;
            int q = rem & 3;
            int gpp = ln >> 2, tgg = ln & 3;
            int rowl = mtb * 16 + gpp + ((q & 1) << 3);
            int k = ks * 8 + tgg + ((q >> 1) << 2);
            int gate = rowl & 3;
            int j = j0 + (rowl >> 2);
            sAu[idx] = cvt_tf32(Wt[gate][(size_t)k * HSZ + j]);
        }
    }

    // per-thread mma row constants
    const int mA = mt * 16 + gp, mB = mA + 8;
    const int gateA = mA & 3, gateB = mB & 3;
    const int jA = j0 + (mA >> 2), jB = j0 + (mB >> 2);
    const size_t rowA = (size_t)gateA * HSZ + jA;
    const size_t rowB = (size_t)gateB * HSZ + jB;
    const int cb = nbase + nh * 16 + tg * 2;

    const float* Bt0[4] = {bgp, bip, bfp, bop};
    const float biasA = Bt0[gateA][jA];
    const float biasB = Bt0[gateB][jB];

    // epilogue mapping: thread -> (jj, 2 batches)
    const int e_jj = tid >> 4;
    const int e_b = (tid & 15) * 2;
    const int e_jglob = j0 + e_jj;
    const int e_bglob = nbase + e_b;

    for (int i = tid; i < 512; i += 256) g_h2[0][ct * 512 + i] = 0.0f;
    if (tid == 0) *(volatile unsigned*)&g_flags[ct * 8] = 0u;
    grid_barrier(gridDim.x);

    float cst0 = 0.0f, cst1 = 0.0f;

    // P prefetch for t=0
    float2 pf0a, pf0b, pf1a, pf1b;
    {
        const float* P0 = g_P;
        pf0a = *(const float2*)&P0[rowA * 128 + cb];
        pf0b = *(const float2*)&P0[rowB * 128 + cb];
        pf1a = *(const float2*)&P0[rowA * 128 + cb + 8];
        pf1b = *(const float2*)&P0[rowB * 128 + cb + 8];
    }

    const unsigned* Abase = sAu + (mt * 64) * 128 + lane * 4;
    const int nAo = (nh * 16 + gp) * 516;
    const int nBo = (nh * 16 + 8 + gp) * 516;

    for (int t = 0; t < TSTEPS; ++t) {
        const float* hb = g_h2[t & 1];
        float* hn = g_h2[(t + 1) & 1];

        float c00 = pf0a.x + biasA, c01 = pf0a.y + biasA;
        float c02 = pf0b.x + biasB, c03 = pf0b.y + biasB;
        float c10 = pf1a.x + biasA, c11 = pf1a.y + biasA;
        float c12 = pf1b.x + biasB, c13 = pf1b.y + biasB;

        if (t + 1 < TSTEPS) {
            const float* Pn = g_P + (size_t)(t + 1) * 2048 * 128;
            pf0a = *(const float2*)&Pn[rowA * 128 + cb];
            pf0b = *(const float2*)&Pn[rowB * 128 + cb];
            pf1a = *(const float2*)&Pn[rowA * 128 + cb + 8];
            pf1b = *(const float2*)&Pn[rowB * 128 + cb + 8];
        }

        // stage h slice: 32 rows x 2KB, single shot
#pragma unroll
        for (int i = 0; i < 16; ++i) {
            int linear = tid + i * 256;
            int row = linear >> 7;
            int slot = (linear & 127) * 4;
            cp16(&sh_h[row * 516 + slot], &hb[(size_t)(nbase + row) * HSZ + slot]);
        }
        asm volatile("cp.async.commit_group;");
        asm volatile("cp.async.wait_group 0;");
        __syncthreads();

        const unsigned* hu = (const unsigned*)sh_h;
#pragma unroll 8
        for (int ks = 0; ks < 64; ++ks) {
            uint4 a = *(const uint4*)&Abase[ks * 128];
            int k0 = ks * 8 + tg;
            unsigned b00 = hu[nAo + k0], b01 = hu[nAo + k0 + 4];
            MMA_TF32(c00, c01, c02, c03, a.x, a.y, a.z, a.w, b00, b01);
            unsigned b10 = hu[nBo + k0], b11 = hu[nBo + k0 + 4];
            MMA_TF32(c10, c11, c12, c13, a.x, a.y, a.z, a.w, b10, b11);
        }

        // write preacts to exchange
        {
            int col0 = nh * 16 + tg * 2;
            *(float2*)&sh_E[mA * 34 + col0]     = make_float2(c00, c01);
            *(float2*)&sh_E[mB * 34 + col0]     = make_float2(c02, c03);
            *(float2*)&sh_E[mA * 34 + col0 + 8] = make_float2(c10, c11);
            *(float2*)&sh_E[mB * 34 + col0 + 8] = make_float2(c12, c13);
        }
        __syncthreads();

        // epilogue: gates for (e_jj, e_b) and (e_jj, e_b+1)
        {
            const float* E0 = &sh_E[(e_jj * 4 + 0) * 34 + e_b];
            const float* E1 = &sh_E[(e_jj * 4 + 1) * 34 + e_b];
            const float* E2 = &sh_E[(e_jj * 4 + 2) * 34 + e_b];
            const float* E3 = &sh_E[(e_jj * 4 + 3) * 34 + e_b];
            float gv0 = fast_tanh(E0[0]),    gv1 = fast_tanh(E0[1]);
            float iv0 = fast_sigmoid(E1[0]), iv1 = fast_sigmoid(E1[1]);
            float fv0 = fast_sigmoid(E2[0]), fv1 = fast_sigmoid(E2[1]);
            float ov0 = fast_sigmoid(E3[0]), ov1 = fast_sigmoid(E3[1]);
            cst0 = gv0 * iv0 + cst0 * fv0;
            cst1 = gv1 * iv1 + cst1 * fv1;
            ((unsigned*)hn)[(size_t)e_bglob * HSZ + e_jglob] =
                cvt_tf32(fast_tanh(cst0) * ov0);
            ((unsigned*)hn)[(size_t)(e_bglob + 1) * HSZ + e_jglob] =
                cvt_tf32(fast_tanh(cst1) * ov1);
        }

        flag_barrier_grp(ct, ng, (unsigned)(t + 1));
    }
}

// ---------------------------------------------------------------------------
// Phase 3: out[b][c] = h_final[b] . Wph[:,c] + bp[c].
// ---------------------------------------------------------------------------
__global__ __launch_bounds__(256) void k_out(
    const float* __restrict__ Wp, const float* __restrict__ bp,
    float* __restrict__ out)
{
    __shared__ float sh[HSZ];
    int b = blockIdx.x;
    const float* h = g_h2[0] + (size_t)b * HSZ;
    for (int i = threadIdx.x; i < HSZ; i += 256) sh[i] = h[i];
    __syncthreads();
    for (int c = threadIdx.x; c < CSZ; c += 256) {
        float acc = 0.0f;
#pragma unroll 8
        for (int k = 0; k < HSZ; ++k)
            acc += sh[k] * Wp[(size_t)k * CSZ + c];
        out[b * CSZ + c] = acc + bp[c];
    }
}

// ---------------------------------------------------------------------------

extern "C" void kernel_launch(void* const* d_in, const int* in_sizes, int n_in,
                              void* d_out, int out_size) {
    const float* x   = (const float*)d_in[0];
    const float* Wgx = (const float*)d_in[1];
    const float* Wgh = (const float*)d_in[2];
    const float* bg  = (const float*)d_in[3];
    const float* Wix = (const float*)d_in[4];
    const float* Wih = (const float*)d_in[5];
    const float* bi  = (const float*)d_in[6];
    const float* Wfx = (const float*)d_in[7];
    const float* Wfh = (const float*)d_in[8];
    const float* bf  = (const float*)d_in[9];
    const float* Wox = (const float*)d_in[10];
    const float* Woh = (const float*)d_in[11];
    const float* bo  = (const float*)d_in[12];
    const float* Wph = (const float*)d_in[13];
    const float* bp  = (const float*)d_in[14];
    float* out = (float*)d_out;

    (void)in_sizes; (void)n_in; (void)out_size;

    const int smem_xp = 34816 * 4;     // 139264 B
    const int smem_rnn = 51456 * 4;    // 205824 B
    cudaFuncSetAttribute(k_xproj2, cudaFuncAttributeMaxDynamicSharedMemorySize, smem_xp);
    cudaFuncSetAttribute(k_rnn2,   cudaFuncAttributeMaxDynamicSharedMemorySize, smem_rnn);

    k_prep_w<<<2048, 256>>>(Wgx, Wix, Wfx, Wox);
    k_prep_x<<<dim3(TSTEPS, BSZ), 64>>>(x);
    k_xproj2<<<dim3(16, TSTEPS), 256, smem_xp>>>();
    k_rnn2<<<128, 256, smem_rnn>>>(Wgh, Wih, Wfh, Woh, bg, bi, bf, bo);
    k_out<<<BSZ, 256>>>(Wph, bp, out);
}